// round 17
// baseline (speedup 1.0000x reference)
#include <cuda_runtime.h>

#define NB 512
#define C_IN 32
#define F1 64
#define F2 128
#define BN_EPS 1e-5f
#define PARTS 8
#define NBLK (NB * PARTS)   // 4096 streaming blocks
#define TB 64               // tail grid (co-resident -> spin barrier safe)
#define TT 256

// ---- scratch (no allocations allowed; zero-initialized at load) ----
__device__ float g_part[PARTS * NB * C_IN];   // per-part channel sums (512 KB)
__device__ float g_meanT[C_IN * NB];          // segment means, [ch][row]
__device__ float g_hT[F1 * NB];               // fc1 activations, [col][row]
__device__ float g_s1[F1], g_o1[F1];          // BN1 affine
__device__ int      g_segcnt[NB];             // per-segment part counters
__device__ unsigned g_barcnt;                 // tail grid barrier

// scoped acq_rel atomic add (no full membar on the retirement path)
__device__ __forceinline__ int atom_add_acqrel_gpu(int* p, int v) {
    int old;
    asm volatile("atom.acq_rel.gpu.global.add.s32 %0, [%1], %2;"
                 : "=r"(old) : "l"(p), "r"(v) : "memory");
    return old;
}

// ---------------------------------------------------------------------------
// K1: streaming partial sums + embedded mean finalize.
// 4096 blocks = 512 segments x 8 parts. After storing its partial, each block
// does ONE scoped acq_rel atomic on its segment counter; the 8th arriver
// (release of all 7 prior partials paired with its acquire) reduces the 8
// partials -> g_meanT with 32 threads (8 coalesced lines) and resets the
// counter for the next graph replay. No membar.gpu anywhere.
// ---------------------------------------------------------------------------
__global__ void __launch_bounds__(256) k_segpart(const float4* __restrict__ x,
                                                 const int* __restrict__ len) {
    __shared__ int    sl[256];
    __shared__ float4 red[256];
    __shared__ int    sarr;

    const int bid = blockIdx.x;
    const int seg = bid >> 3;          // 8 parts per segment, adjacent bids
    const int p   = bid & (PARTS - 1);
    const int tid = threadIdx.x;

    if (bid == 0 && tid == 0) g_barcnt = 0;   // reset tail barrier (pre-trigger)

    // --- segment offset: sum of len[i] for i < seg (block-redundant) ---
    {
        int v = 0;
        if (tid < seg)       v += len[tid];
        if (tid + 256 < seg) v += len[tid + 256];
        sl[tid] = v;
    }
    __syncthreads();
    #pragma unroll
    for (int st = 128; st > 0; st >>= 1) {
        if (tid < st) sl[tid] += sl[tid + st];
        __syncthreads();
    }
    const int off = sl[0];
    const int L   = len[seg];
    const int r0  = off + (L * p)       / PARTS;
    const int r1  = off + (L * (p + 1)) / PARTS;

    // --- stream rows [r0, r1): 8 independent float4 loads in flight ---
    {
        int js = r0 * 8 + tid;
        int je = r1 * 8;
        float4 a0 = make_float4(0.f,0.f,0.f,0.f);
        float4 a1 = a0, a2 = a0, a3 = a0;
        float4 a4 = a0, a5 = a0, a6 = a0, a7 = a0;
        int j = js;
        for (; j + 1792 < je; j += 2048) {
            float4 v0 = __ldcs(&x[j]);
            float4 v1 = __ldcs(&x[j + 256]);
            float4 v2 = __ldcs(&x[j + 512]);
            float4 v3 = __ldcs(&x[j + 768]);
            float4 v4 = __ldcs(&x[j + 1024]);
            float4 v5 = __ldcs(&x[j + 1280]);
            float4 v6 = __ldcs(&x[j + 1536]);
            float4 v7 = __ldcs(&x[j + 1792]);
            a0.x += v0.x; a0.y += v0.y; a0.z += v0.z; a0.w += v0.w;
            a1.x += v1.x; a1.y += v1.y; a1.z += v1.z; a1.w += v1.w;
            a2.x += v2.x; a2.y += v2.y; a2.z += v2.z; a2.w += v2.w;
            a3.x += v3.x; a3.y += v3.y; a3.z += v3.z; a3.w += v3.w;
            a4.x += v4.x; a4.y += v4.y; a4.z += v4.z; a4.w += v4.w;
            a5.x += v5.x; a5.y += v5.y; a5.z += v5.z; a5.w += v5.w;
            a6.x += v6.x; a6.y += v6.y; a6.z += v6.z; a6.w += v6.w;
            a7.x += v7.x; a7.y += v7.y; a7.z += v7.z; a7.w += v7.w;
        }
        for (; j < je; j += 256) {
            float4 v0 = __ldcs(&x[j]);
            a0.x += v0.x; a0.y += v0.y; a0.z += v0.z; a0.w += v0.w;
        }
        // fixed-order pairwise combine (deterministic)
        a0.x += a4.x; a0.y += a4.y; a0.z += a4.z; a0.w += a4.w;
        a1.x += a5.x; a1.y += a5.y; a1.z += a5.z; a1.w += a5.w;
        a2.x += a6.x; a2.y += a6.y; a2.z += a6.z; a2.w += a6.w;
        a3.x += a7.x; a3.y += a7.y; a3.z += a7.z; a3.w += a7.w;
        a0.x += a2.x; a0.y += a2.y; a0.z += a2.z; a0.w += a2.w;
        a1.x += a3.x; a1.y += a3.y; a1.z += a3.z; a1.w += a3.w;
        a0.x += a1.x; a0.y += a1.y; a0.z += a1.z; a0.w += a1.w;

        red[tid] = a0;
    }
    __syncthreads();
    #pragma unroll
    for (int st = 128; st >= 8; st >>= 1) {
        if (tid < st) {
            float4 o = red[tid + st];
            red[tid].x += o.x; red[tid].y += o.y;
            red[tid].z += o.z; red[tid].w += o.w;
        }
        __syncthreads();
    }
    if (tid < 8)
        ((float4*)g_part)[(p * NB + seg) * 8 + tid] = red[tid];
    __syncthreads();

    // --- single scoped acq_rel atomic; 8th arriver finalizes the mean ---
    if (tid == 0)
        sarr = atom_add_acqrel_gpu(&g_segcnt[seg], 1);
    __syncthreads();
    if (sarr == PARTS - 1) {
        if (tid < C_IN) {
            float s = 0.f;
            #pragma unroll
            for (int q = 0; q < PARTS; q++)
                s += g_part[(q * NB + seg) * C_IN + tid];   // 8 coalesced lines
            g_meanT[tid * NB + seg] = s / (float)L;
        }
        if (tid == 0) g_segcnt[seg] = 0;   // reset for next replay
    }

    // allow the dependent tail kernel to begin launching
    asm volatile("griddepcontrol.launch_dependents;");
}

// ---------------------------------------------------------------------------
// software grid barrier (TB blocks, all co-resident)
// ---------------------------------------------------------------------------
__device__ __forceinline__ void grid_bar(unsigned target) {
    __syncthreads();
    if (threadIdx.x == 0) {
        __threadfence();
        atomicAdd(&g_barcnt, 1u);
        while (*((volatile unsigned*)&g_barcnt) < target) { }
        __threadfence();
    }
    __syncthreads();
}

// ---------------------------------------------------------------------------
// K2: tail, 64 blocks x 256 threads, ONE grid barrier (A0 now lives in K1).
// Weight-slice staging runs BEFORE griddepcontrol.wait (overlaps K1 drain).
//   A: fc1 column b + BN1 stats (block-local)
//   B: BN1+relu+fc2 + BN2 stats + apply (block-local, out cols 2b, 2b+1)
// ---------------------------------------------------------------------------
__global__ void __launch_bounds__(TT) k_tail(
    const float* __restrict__ W1, const float* __restrict__ b1,
    const float* __restrict__ g1, const float* __restrict__ be1,
    const float* __restrict__ W2, const float* __restrict__ b2,
    const float* __restrict__ g2, const float* __restrict__ be2,
    float* __restrict__ out)
{
    __shared__ float sred[2 * TT];
    __shared__ float sW1[C_IN];          // W1[:, b]
    __shared__ float sW2a[F1], sW2b[F1]; // W2[:, 2b], W2[:, 2b+1]
    __shared__ float ss1[F1], so1[F1];
    __shared__ float sbias[2];
    __shared__ float sbn2[4];

    const int tid = threadIdx.x;
    const int b   = blockIdx.x;
    const int c0  = 2 * b, c1 = 2 * b + 1;

    // ---- stage weight slices (independent of K1) — overlaps K1 drain ----
    if (tid < C_IN)                 sW1[tid] = W1[tid * F1 + b];
    else if (tid < C_IN + F1)       sW2a[tid - C_IN] = W2[(tid - C_IN) * F2 + c0];
    else if (tid < C_IN + 2 * F1)   sW2b[tid - C_IN - F1] = W2[(tid - C_IN - F1) * F2 + c1];
    else if (tid == C_IN + 2 * F1)     sbias[0] = b2[c0];
    else if (tid == C_IN + 2 * F1 + 1) sbias[1] = b2[c1];

    // wait for ALL of k_segpart's writes (incl. g_meanT) to be visible
    asm volatile("griddepcontrol.wait;" ::: "memory");

    // ---- A: column c=b of h = mean @ W1 + b1, plus BN1 stats ----
    {
        float acc0 = __ldg(&b1[b]), acc1 = acc0;
        #pragma unroll
        for (int k = 0; k < C_IN; k++) {
            float w = sW1[k];
            acc0 = fmaf(g_meanT[k * NB + tid],       w, acc0);   // coalesced
            acc1 = fmaf(g_meanT[k * NB + tid + 256], w, acc1);   // coalesced
        }
        g_hT[b * NB + tid]       = acc0;
        g_hT[b * NB + tid + 256] = acc1;

        sred[tid]      = acc0 + acc1;
        sred[TT + tid] = acc0 * acc0 + acc1 * acc1;
        __syncthreads();
        #pragma unroll
        for (int st = 128; st > 0; st >>= 1) {
            if (tid < st) {
                sred[tid]      += sred[tid + st];
                sred[TT + tid] += sred[TT + tid + st];
            }
            __syncthreads();
        }
        if (tid == 0) {
            float mu  = sred[0]  * (1.0f / (float)NB);
            float var = sred[TT] * (1.0f / (float)NB) - mu * mu;
            float sc  = g1[b] * rsqrtf(var + BN_EPS);
            g_s1[b] = sc;
            g_o1[b] = be1[b] - mu * sc;
        }
    }
    grid_bar(TB);

    if (tid < F1) { ss1[tid] = g_s1[tid]; so1[tid] = g_o1[tid]; }
    __syncthreads();

    // ---- B: out cols c0, c1; rows tid and tid+256 ----
    {
        float a00 = sbias[0], a01 = sbias[1];
        float a10 = a00,      a11 = a01;
        #pragma unroll 16
        for (int k = 0; k < F1; k++) {
            float h0 = g_hT[k * NB + tid];          // coalesced
            float h1 = g_hT[k * NB + tid + 256];    // coalesced
            float sc = ss1[k], of = so1[k];
            float r0 = fmaxf(fmaf(h0, sc, of), 0.f);
            float r1 = fmaxf(fmaf(h1, sc, of), 0.f);
            float w0 = sW2a[k];
            float w1 = sW2b[k];
            a00 = fmaf(r0, w0, a00);
            a01 = fmaf(r0, w1, a01);
            a10 = fmaf(r1, w0, a10);
            a11 = fmaf(r1, w1, a11);
        }

        // BN2 stats col c0 (deterministic tree)
        sred[tid]      = a00 + a10;
        sred[TT + tid] = a00 * a00 + a10 * a10;
        __syncthreads();
        #pragma unroll
        for (int st = 128; st > 0; st >>= 1) {
            if (tid < st) {
                sred[tid]      += sred[tid + st];
                sred[TT + tid] += sred[TT + tid + st];
            }
            __syncthreads();
        }
        if (tid == 0) {
            float mu  = sred[0]  * (1.0f / (float)NB);
            float var = sred[TT] * (1.0f / (float)NB) - mu * mu;
            float sc  = g2[c0] * rsqrtf(var + BN_EPS);
            sbn2[0] = sc;
            sbn2[1] = be2[c0] - mu * sc;
        }
        __syncthreads();

        // BN2 stats col c1
        sred[tid]      = a01 + a11;
        sred[TT + tid] = a01 * a01 + a11 * a11;
        __syncthreads();
        #pragma unroll
        for (int st = 128; st > 0; st >>= 1) {
            if (tid < st) {
                sred[tid]      += sred[tid + st];
                sred[TT + tid] += sred[TT + tid + st];
            }
            __syncthreads();
        }
        if (tid == 0) {
            float mu  = sred[0]  * (1.0f / (float)NB);
            float var = sred[TT] * (1.0f / (float)NB) - mu * mu;
            float sc  = g2[c1] * rsqrtf(var + BN_EPS);
            sbn2[2] = sc;
            sbn2[3] = be2[c1] - mu * sc;
        }
        __syncthreads();

        float s0 = sbn2[0], o0 = sbn2[1], s1 = sbn2[2], o1 = sbn2[3];
        out[tid * F2 + c0]         = fmaf(a00, s0, o0);
        out[tid * F2 + c1]         = fmaf(a01, s1, o1);
        out[(tid + 256) * F2 + c0] = fmaf(a10, s0, o0);
        out[(tid + 256) * F2 + c1] = fmaf(a11, s1, o1);
    }
}

// ---------------------------------------------------------------------------
extern "C" void kernel_launch(void* const* d_in, const int* in_sizes, int n_in,
                              void* d_out, int out_size) {
    const float* x     = (const float*)d_in[0];
    const int*   len   = (const int*)  d_in[1];
    const float* W1    = (const float*)d_in[2];
    const float* b1    = (const float*)d_in[3];
    const float* g1    = (const float*)d_in[4];
    const float* beta1 = (const float*)d_in[5];
    const float* W2    = (const float*)d_in[6];
    const float* b2    = (const float*)d_in[7];
    const float* g2    = (const float*)d_in[8];
    const float* beta2 = (const float*)d_in[9];
    float* out = (float*)d_out;

    k_segpart<<<NBLK, 256>>>((const float4*)x, len);

    // PDL: tail may begin launching once segpart triggers launch_dependents;
    // its pre-wait staging overlaps segpart's drain.
    cudaLaunchConfig_t cfg = {};
    cfg.gridDim  = dim3(TB, 1, 1);
    cfg.blockDim = dim3(TT, 1, 1);
    cfg.dynamicSmemBytes = 0;
    cfg.stream = 0;
    cudaLaunchAttribute attrs[1];
    attrs[0].id = cudaLaunchAttributeProgrammaticStreamSerialization;
    attrs[0].val.programmaticStreamSerializationAllowed = 1;
    cfg.attrs = attrs;
    cfg.numAttrs = 1;
    cudaLaunchKernelEx(&cfg, k_tail, W1, b1, g1, beta1,
                       W2, b2, g2, beta2, out);
}